// round 12
// baseline (speedup 1.0000x reference)
#include <cuda_runtime.h>
#include <math.h>

#define T_SEQ 512
#define NB    64
#define NI    256
#define NH    512

// Per-CTA progress flags: g_prog[bt][jt], 256 B apart. MONOTONIC across
// graph replays (each launch adds exactly T_SEQ per flag; single writer).
// A CTA reads its OWN flag at start for the launch base — it cannot have
// advanced yet, and all flags are equal at launch start.
__device__ unsigned g_prog[128 * 64];

typedef unsigned long long ull;

// Packed 2x fp32 FMA (sm_10x f32x2 pipe).
#define FFMA2(d, a, b, c) \
    asm("fma.rn.f32x2 %0, %1, %2, %3;" : "=l"(d) : "l"(a), "l"(b), "l"(c))

__device__ __forceinline__ float2 unpack2(ull v) {
    unsigned lo, hi;
    asm("mov.b64 {%0, %1}, %2;" : "=r"(lo), "=r"(hi) : "l"(v));
    return make_float2(__uint_as_float(lo), __uint_as_float(hi));
}

__device__ __forceinline__ unsigned smem_u32(const void* p) {
    return (unsigned)__cvta_generic_to_shared(p);
}
__device__ __forceinline__ void mbar_init(unsigned a, unsigned cnt) {
    asm volatile("mbarrier.init.shared.b64 [%0], %1;" :: "r"(a), "r"(cnt)
                 : "memory");
}
__device__ __forceinline__ void mbar_arrive(unsigned a) {
    asm volatile("mbarrier.arrive.release.cta.shared.b64 _, [%0];"
                 :: "r"(a) : "memory");
}
__device__ __forceinline__ void mbar_wait(unsigned a, unsigned parity) {
    unsigned done;
    do {
        asm volatile(
            "{\n\t.reg .pred p;\n\t"
            "mbarrier.try_wait.parity.acquire.cta.shared.b64 p, [%1], %2, 0x989680;\n\t"
            "selp.b32 %0, 1, 0, p;\n\t}"
            : "=r"(done) : "r"(a), "r"(parity) : "memory");
    } while (!done);
}
// Poll a progress flag until it reaches `need` (acquire: orders later loads).
__device__ __forceinline__ void flag_wait(const unsigned* f, unsigned need) {
    unsigned v;
    do {
        asm volatile("ld.acquire.gpu.u32 %0, [%1];"
                     : "=r"(v) : "l"(f) : "memory");
    } while ((int)(v - need) < 0);
}

// ---- dynamic smem layout (float indices) ----------------------------------
#define HS_OFF    0       // h tile [8 b][512]                  (16 KB)
#define PART_OFF  4096    // consumer partials [8 ks][8 b][32]  ( 8 KB)
#define RING_OFF  6144    // pre ring [2 slot][8 b][32 j]       ( 2 KB)
#define XB_OFF    6656    // x tile [8 b][256]                  ( 8 KB)
#define PP_OFF    8704    // producer partials [4 pw][8 b][32]  ( 4 KB)
#define MBAR_OFF  9728    // full0, full1, empty0, empty1 (4x u64) + base
#define SM_FLOATS 9744

#define RT 384   // warps 0..7 consumers (256 thr), warps 8..11 producers

__global__ __launch_bounds__(RT, 1) void rnn_fused(
    const float* __restrict__ x,     // [T][B][I]
    const float* __restrict__ h0,    // [B][H]
    const float* __restrict__ Wih,   // [H][I]
    const float* __restrict__ Whh,   // [H][H]
    const float* __restrict__ bih,   // [H]
    const float* __restrict__ bhh,   // [H]
    float* __restrict__ hseq,        // [T][B][H]
    float* __restrict__ hlast)       // [B][H] or nullptr
{
    extern __shared__ float sm[];

    const int tid  = threadIdx.x;
    const int lane = tid & 31;
    const int warp = tid >> 5;
    const int jt   = blockIdx.x & 15;
    const int bt   = blockIdx.x >> 4;
    const int j0   = jt * 32;
    const int b0   = bt * 8;

    unsigned* const flag_own = &g_prog[(bt * 16 + jt) * 64];

    const unsigned a_full0  = smem_u32(sm + MBAR_OFF);       // +0 / +8
    const unsigned a_empty0 = smem_u32(sm + MBAR_OFF + 4);   // +0 / +8
    unsigned* const pbase   = (unsigned*)(sm + MBAR_OFF + 8);

    if (tid == 0) {
        mbar_init(a_full0,      4);   // 4 producer warps arrive
        mbar_init(a_full0  + 8, 4);
        mbar_init(a_empty0,     8);   // 8 consumer warps arrive
        mbar_init(a_empty0 + 8, 8);
        *pbase = *(volatile unsigned*)flag_own;   // own flag: launch base
    }
    __syncthreads();
    const unsigned base = *pbase;

    if (warp < 8) {
        // ================= CONSUMER (recurrence) =================
        const int ks = warp;          // k-slice this warp computes
        const int k0 = ks * 64;
        // The two CTAs that produce my h slice.
        const unsigned* const flagA = &g_prog[(bt * 16 + 2 * ks)     * 64];
        const unsigned* const flagB = &g_prog[(bt * 16 + 2 * ks + 1) * 64];

        // W_hh[j0+lane][k0..k0+63] -> 32 packed-pair registers.
        ull w2[32];
        {
            const ulonglong2* wp =
                (const ulonglong2*)(Whh + (size_t)(j0 + lane) * NH + k0);
#pragma unroll
            for (int c = 0; c < 16; ++c) {
                ulonglong2 v = __ldg(wp + c);
                w2[2 * c]     = v.x;
                w2[2 * c + 1] = v.y;
            }
        }

        unsigned pf0 = 0, pf1 = 0;    // full-ring parities per slot

        for (int t = 0; t < T_SEQ; ++t) {
            const int slot = t & 1;

            // Dependency-only wait: my 2 producers must have finished t-1.
            if (t > 0) {
                const unsigned need = base + (unsigned)t;
                flag_wait(flagA, need);
                flag_wait(flagB, need);
            }

            // Stage OWN h slice (8 batches x 64 cols) — warp-private.
            const float* hprev = t ? hseq + (size_t)(t - 1) * NB * NH : h0;
#pragma unroll
            for (int i = 0; i < 4; ++i) {
                int idx = lane + 32 * i;       // 0..127 float4 slots
                int row = idx >> 4;
                int c4  = idx & 15;
                float4 v = __ldcg((const float4*)(hprev +
                              (size_t)(b0 + row) * NH + k0 + c4 * 4));
                *(float4*)(sm + HS_OFF + row * NH + k0 + c4 * 4) = v;
            }
            __syncwarp();

            // 8 partial dots (one per batch), K-slice 64, packed FMAs.
            float accs[8];
#pragma unroll
            for (int b = 0; b < 8; ++b) {
                const ulonglong2* hp =
                    (const ulonglong2*)(sm + HS_OFF + b * NH + k0);
                ull a0 = 0ull, a1 = 0ull;
#pragma unroll
                for (int c = 0; c < 16; ++c) {
                    ulonglong2 hv = hp[c];   // broadcast LDS.128 (1 phase)
                    FFMA2(a0, w2[2 * c],     hv.x, a0);
                    FFMA2(a1, w2[2 * c + 1], hv.y, a1);
                }
                float2 f0 = unpack2(a0);
                float2 f1 = unpack2(a1);
                accs[b] = (f0.x + f0.y) + (f1.x + f1.y);
            }
#pragma unroll
            for (int b = 0; b < 8; ++b)
                sm[PART_OFF + ks * 256 + b * 32 + lane] = accs[b];
            asm volatile("bar.sync 1, 256;" ::: "memory");

            // Reduce role: warp = batch, lane = column j0+lane.
            float s = 0.f;
#pragma unroll
            for (int w = 0; w < 8; ++w)
                s += sm[PART_OFF + w * 256 + warp * 32 + lane];

            // pre[t] ring read (producers had a full step of slack).
            if (slot) { mbar_wait(a_full0 + 8, pf1); pf1 ^= 1; }
            else      { mbar_wait(a_full0,     pf0); pf0 ^= 1; }
            const float pre = sm[RING_OFF + slot * 256 + warp * 32 + lane];

            const float hv = tanhf(s + pre);
            const int   bo = b0 + warp;
            hseq[((size_t)t * NB + bo) * NH + j0 + lane] = hv;
            if (t == T_SEQ - 1 && hlast)
                hlast[(size_t)bo * NH + j0 + lane] = hv;

            // Ring slot consumed -> producers may refill it.
            __syncwarp();
            if (lane == 0) mbar_arrive(a_empty0 + (unsigned)slot * 8);

            // All 8 warps' h stores drained, then publish progress.
            asm volatile("bar.sync 1, 256;" ::: "memory");
            if (tid == 0)
                asm volatile("st.release.gpu.u32 [%0], %1;"
                             :: "l"(flag_own), "r"(base + (unsigned)(t + 1))
                             : "memory");
        }
    } else {
        // ============ PRODUCER (input projection, smem-lean) ============
        const int pw   = warp - 8;    // 0..3
        const int k0   = pw * 64;     // producer k-slice of NI
        const int ptid = tid - 256;   // 0..127

        // W_ih[j0+lane][k0..k0+63] -> 32 packed-pair registers.
        ull wi2[32];
        {
            const ulonglong2* wp =
                (const ulonglong2*)(Wih + (size_t)(j0 + lane) * NI + k0);
#pragma unroll
            for (int c = 0; c < 16; ++c) {
                ulonglong2 v = __ldg(wp + c);
                wi2[2 * c]     = v.x;
                wi2[2 * c + 1] = v.y;
            }
        }
        const float bias = __ldg(bih + j0 + lane) + __ldg(bhh + j0 + lane);
        unsigned pe0 = 0, pe1 = 0;

        for (int t = 0; t < T_SEQ; ++t) {
            const int slot = t & 1;

            // Stage x tile (8 batches x 256) — 128 threads x 4 float4.
#pragma unroll
            for (int i = 0; i < 4; ++i) {
                int idx = ptid + 128 * i;      // 0..511 float4 slots
                int row = idx >> 6;
                int c4  = idx & 63;
                float4 v = __ldg((const float4*)(x +
                              ((size_t)t * NB + b0 + row) * NI + c4 * 4));
                *(float4*)(sm + XB_OFF + row * NI + c4 * 4) = v;
            }
            asm volatile("bar.sync 2, 128;" ::: "memory");

            // 8 partial dots over this warp's 64-k slice (broadcast LDS).
            float pacc[8];
#pragma unroll
            for (int b = 0; b < 8; ++b) {
                const ulonglong2* xp =
                    (const ulonglong2*)(sm + XB_OFF + b * NI + k0);
                ull a0 = 0ull, a1 = 0ull;
#pragma unroll
                for (int c = 0; c < 16; ++c) {
                    ulonglong2 xv = xp[c];   // broadcast LDS.128 (1 phase)
                    FFMA2(a0, wi2[2 * c],     xv.x, a0);
                    FFMA2(a1, wi2[2 * c + 1], xv.y, a1);
                }
                float2 f0 = unpack2(a0);
                float2 f1 = unpack2(a1);
                pacc[b] = (f0.x + f0.y) + (f1.x + f1.y);
            }
#pragma unroll
            for (int b = 0; b < 8; ++b)
                sm[PP_OFF + pw * 256 + b * 32 + lane] = pacc[b];
            asm volatile("bar.sync 2, 128;" ::: "memory");

            // Wait for ring slot to be free (consumers of step t-2 done).
            if (t >= 2) {
                if (slot) { mbar_wait(a_empty0 + 8, pe1); pe1 ^= 1; }
                else      { mbar_wait(a_empty0,     pe0); pe0 ^= 1; }
            }

            // Reduce: warp pw emits batches 2pw and 2pw+1.
#pragma unroll
            for (int r = 0; r < 2; ++r) {
                const int b = pw * 2 + r;
                float s = bias;
#pragma unroll
                for (int w = 0; w < 4; ++w)
                    s += sm[PP_OFF + w * 256 + b * 32 + lane];
                sm[RING_OFF + slot * 256 + b * 32 + lane] = s;
            }
            __syncwarp();
            if (lane == 0) mbar_arrive(a_full0 + (unsigned)slot * 8);
        }
    }
}

// ---------------------------------------------------------------------------
extern "C" void kernel_launch(void* const* d_in, const int* in_sizes, int n_in,
                              void* d_out, int out_size)
{
    const float* x   = (const float*)d_in[0];
    const float* h0  = (const float*)d_in[1];
    const float* Wih = (const float*)d_in[2];
    const float* Whh = (const float*)d_in[3];
    const float* bih = (const float*)d_in[4];
    const float* bhh = (const float*)d_in[5];
    float* out = (float*)d_out;

    float* hlast = nullptr;
    if (out_size >= (int)((size_t)T_SEQ * NB * NH + NB * NH))
        hlast = out + (size_t)T_SEQ * NB * NH;

    const size_t smem = SM_FLOATS * sizeof(float);   // 38976 B
    cudaFuncSetAttribute(rnn_fused,
                         cudaFuncAttributeMaxDynamicSharedMemorySize,
                         (int)smem);
    rnn_fused<<<128, RT, smem>>>(x, h0, Wih, Whh, bih, bhh, out, hlast);
}